// round 14
// baseline (speedup 1.0000x reference)
#include <cuda_runtime.h>
#include <cuda_fp16.h>
#include <cstdint>

#define Bb 64
#define Nn 17
#define Tt 512
#define Cc 64

// scratch: [B][64(c2)][17(n)][512(t)] in fp16 (71MB)
__device__ __half g_scratch_h[Bb * 64 * Nn * Tt];

// ---------------- packed f32x2 helpers (sm_10x) ----------------------------
__device__ __forceinline__ unsigned long long pk2(float lo, float hi) {
    unsigned long long r;
    asm("mov.b64 %0, {%1, %2};" : "=l"(r) : "f"(lo), "f"(hi));
    return r;
}
__device__ __forceinline__ void upk2(unsigned long long v, float& lo, float& hi) {
    asm("mov.b64 {%0, %1}, %2;" : "=f"(lo), "=f"(hi) : "l"(v));
}
__device__ __forceinline__ unsigned long long mul2(unsigned long long a, unsigned long long b) {
    unsigned long long r;
    asm("mul.rn.f32x2 %0, %1, %2;" : "=l"(r) : "l"(a), "l"(b));
    return r;
}
__device__ __forceinline__ unsigned long long fma2p(unsigned long long a, unsigned long long b, unsigned long long c) {
    unsigned long long r;
    asm("fma.rn.f32x2 %0, %1, %2, %3;" : "=l"(r) : "l"(a), "l"(b), "l"(c));
    return r;
}
__device__ __forceinline__ float tanh_ap(float x) {
    float r;
    asm("tanh.approx.f32 %0, %1;" : "=f"(r) : "f"(x));
    return r;
}
// packed tanh-gelu on 2 values
__device__ __forceinline__ unsigned long long gelu2(unsigned long long z,
    unsigned long long C0447, unsigned long long C0798, unsigned long long ONE2, unsigned long long HALF2)
{
    unsigned long long w = mul2(z, z);
    unsigned long long p = fma2p(w, C0447, ONE2);     // 1 + 0.044715 z^2
    unsigned long long q = mul2(z, C0798);            // 0.79788456 z
    unsigned long long u = mul2(p, q);
    float u0, u1; upk2(u, u0, u1);
    unsigned long long tp = pk2(tanh_ap(u0), tanh_ap(u1));
    unsigned long long hv = mul2(z, HALF2);
    return fma2p(tp, hv, hv);                          // 0.5 z (1 + tanh)
}

__device__ __forceinline__ unsigned to_tf32(float f) {
    unsigned r;
    asm("cvt.rna.tf32.f32 %0, %1;" : "=r"(r) : "f"(f));
    return r;
}

// unpack half2 (as uint) -> packed f32x2 ull
__device__ __forceinline__ unsigned long long h2_to_p2(unsigned hv) {
    __half2 h = *(__half2*)&hv;
    float2 f = __half22float2(h);
    return pk2(f.x, f.y);
}
// packed f32x2 -> half2 (as uint)
__device__ __forceinline__ unsigned p2_to_h2(unsigned long long p) {
    float lo, hi; upk2(p, lo, hi);
    __half2 h = __floats2half2_rn(lo, hi);
    return *(unsigned*)&h;
}

// ---------------------------------------------------------------------------
// Kernel A: one block per (b, c2).
// ---------------------------------------------------------------------------
#define OFF_SX    0
#define OFF_SH    9248
#define OFF_SW    18496
#define OFF_BIAS  22848          /* 289 used, padded to 292 */
#define OFF_SS    23140
#define OFF_ST    23684
#define OFF_DIV   24228
#define OFF_SCL   24772
#define OFF_SA    25316
#define SMEM_A_FLOATS 25348

__global__ void __launch_bounds__(768, 2) stconv_gat_tcn(
    const float* __restrict__ x, const int* __restrict__ adj,
    const float* __restrict__ W, const float* __restrict__ av,
    const float* __restrict__ w1, const float* __restrict__ gamma1, const float* __restrict__ beta1,
    const float* __restrict__ w2, const float* __restrict__ gamma2, const float* __restrict__ beta2)
{
    extern __shared__ float sm[];
    float* sx    = sm + OFF_SX;
    float* sh    = sm + OFF_SH;
    float* sW    = sm + OFF_SW;
    float* sbias = sm + OFF_BIAS;
    float* ss    = sm + OFF_SS;
    float* st    = sm + OFF_ST;
    float* sdiv  = sm + OFF_DIV;
    float* sscl  = sm + OFF_SCL;
    float* sa    = sm + OFF_SA;

    const int tid = threadIdx.x;
    const int b   = blockIdx.x >> 6;
    const int c2  = blockIdx.x & 63;
    const int t0  = c2 << 3;

    // ---- phase 1: loads -------------------------------------------------
    {
        const float4* xg = (const float4*)(x + ((size_t)(b * Nn) * Tt + t0) * Cc);
        for (int i = tid; i < 2176; i += 768) {
            int q  = i & 15;
            int nt = i >> 4;
            int n  = nt % 17;
            int t  = nt / 17;
            float4 v = xg[((size_t)n * Tt + t) * 16 + q];
            *(float4*)(sx + (t * 17 + n) * 68 + q * 4) = v;
        }
        for (int i = tid; i < 1024; i += 768) {
            int o = i >> 4, c4 = i & 15;
            float4 v = ((const float4*)W)[i];
            v.x = __uint_as_float(to_tf32(v.x));
            v.y = __uint_as_float(to_tf32(v.y));
            v.z = __uint_as_float(to_tf32(v.z));
            v.w = __uint_as_float(to_tf32(v.w));
            *(float4*)(sW + o * 68 + c4 * 4) = v;
        }
        if (tid < 289)
            sbias[tid] = (adj[b * 289 + tid] == 0) ? -1e9f : 0.0f;
        if (tid < 32) sa[tid] = av[tid];
    }
    __syncthreads();

    // ---- phase 2: GEMM h = x * W^T (tf32 MMA, m16n32 units) -------------
    {
        const int warp = tid >> 5, lane = tid & 31;
        const int lr = lane >> 2, lc = lane & 3;
        for (int unit = warp; unit < 18; unit += 24) {
            const int mt = unit >> 1;        // 0..8
            const int nh = unit & 1;         // cols nh*32
            const int m0 = mt << 4;
            const int r0 = m0 + lr;
            const int r1 = (r0 + 8 < 136) ? (r0 + 8) : 135;
            float d[16];
#pragma unroll
            for (int i = 0; i < 16; ++i) d[i] = 0.0f;
#pragma unroll
            for (int k0 = 0; k0 < 8; ++k0) {
                const int kb = k0 * 8 + lc;
                unsigned a0 = __float_as_uint(sx[r0 * 68 + kb]);
                unsigned a1 = __float_as_uint(sx[r1 * 68 + kb]);
                unsigned a2 = __float_as_uint(sx[r0 * 68 + kb + 4]);
                unsigned a3 = __float_as_uint(sx[r1 * 68 + kb + 4]);
#pragma unroll
                for (int j8 = 0; j8 < 4; ++j8) {
                    const int n = nh * 32 + j8 * 8 + lr;
                    unsigned b0 = __float_as_uint(sW[n * 68 + kb]);
                    unsigned b1 = __float_as_uint(sW[n * 68 + kb + 4]);
                    asm("mma.sync.aligned.m16n8k8.row.col.f32.tf32.tf32.f32 "
                        "{%0,%1,%2,%3},{%4,%5,%6,%7},{%8,%9},{%0,%1,%2,%3};"
                        : "+f"(d[j8*4+0]), "+f"(d[j8*4+1]), "+f"(d[j8*4+2]), "+f"(d[j8*4+3])
                        : "r"(a0), "r"(a1), "r"(a2), "r"(a3), "r"(b0), "r"(b1));
                }
            }
#pragma unroll
            for (int j8 = 0; j8 < 4; ++j8) {
                const int col = nh * 32 + j8 * 8 + 2 * lc;
                *(float2*)(sh + r0 * 68 + col) = make_float2(d[j8*4+0], d[j8*4+1]);
                if (mt < 8)
                    *(float2*)(sh + (m0 + 8 + lr) * 68 + col) = make_float2(d[j8*4+2], d[j8*4+3]);
            }
        }
    }
    __syncthreads();

    // ---- phase 3: per-head source/target dots (float4) ------------------
    for (int i = tid; i < 1088; i += 768) {
        int kind = i & 1;
        int hd   = (i >> 1) & 3;
        int row  = i >> 3;
        const float4* hv = (const float4*)(sh + row * 68 + hd * 16);
        const float4* av4 = (const float4*)(sa + kind * 16);
        float acc = 0.0f;
#pragma unroll
        for (int q = 0; q < 4; ++q) {
            float4 h4 = hv[q], a4 = av4[q];
            acc = fmaf(h4.x, a4.x, acc);
            acc = fmaf(h4.y, a4.y, acc);
            acc = fmaf(h4.z, a4.z, acc);
            acc = fmaf(h4.w, a4.w, acc);
        }
        (kind ? st : ss)[row * 4 + hd] = acc;
    }
    __syncthreads();

    // ---- phase 4a: per-(i,h) inv-denominator ----------------------------
    if (tid < 544) {
        int task = tid;
        int hd  = task & 3;
        int row = task >> 2;
        int t   = row / 17;
        int ii  = row - t * 17;
        float sv = ss[row * 4 + hd];
        float den = 0.0f;
#pragma unroll
        for (int j = 0; j < 17; ++j) {
            float e = sv + st[(t * 17 + j) * 4 + hd];
            e = (e > 0.0f) ? e : 0.2f * e;
            den += __expf(e + sbias[ii * 17 + j]);
        }
        sdiv[row * 4 + hd] = __fdividef(1.0f, den);
    }
    __syncthreads();

    // ---- phase 4b: scale[j] = sum_i alpha[i][j] -------------------------
    if (tid < 544) {
        int task = tid;
        int hd  = task & 3;
        int row = task >> 2;
        int t   = row / 17;
        int jj  = row - t * 17;
        float tv = st[row * 4 + hd];
        float acc = 0.0f;
#pragma unroll
        for (int i = 0; i < 17; ++i) {
            int ri = (t * 17 + i) * 4 + hd;
            float e = ss[ri] + tv;
            e = (e > 0.0f) ? e : 0.2f * e;
            acc = fmaf(__expf(e + sbias[i * 17 + jj]), sdiv[ri], acc);
        }
        sscl[row * 4 + hd] = acc;
    }
    __syncthreads();

    // ---- phase 5: g = h*scale + h0  (in place, float4) ------------------
    for (int i = tid; i < 2176; i += 768) {
        int row = i >> 4;
        int c0  = (i & 15) << 2;
        float4 h4 = *(float4*)(sh + row * 68 + c0);
        float4 x4 = *(float4*)(sx + row * 68 + c0);
        float sc  = sscl[row * 4 + (c0 >> 4)];
        h4.x = fmaf(h4.x, sc, x4.x);
        h4.y = fmaf(h4.y, sc, x4.y);
        h4.z = fmaf(h4.z, sc, x4.z);
        h4.w = fmaf(h4.w, sc, x4.w);
        *(float4*)(sh + row * 68 + c0) = h4;
    }
    __syncthreads();

    const unsigned long long C0447 = pk2(0.044715f, 0.044715f);
    const unsigned long long C0798 = pk2(0.7978845608028654f, 0.7978845608028654f);
    const unsigned long long ONE2  = pk2(1.0f, 1.0f);
    const unsigned long long HALF2 = pk2(0.5f, 0.5f);

    // ---- phase 6: conv1 + BN + GELU -> z1 in fp16 (reuse sx area) -------
    const float w10 = w1[c2 * 3 + 0], w11 = w1[c2 * 3 + 1], w12 = w1[c2 * 3 + 2];
    const float k1  = gamma1[c2] * rsqrtf(1.0f + 1e-5f);
    const float bb1 = beta1[c2];
    const float w20 = w2[c2 * 3 + 0], w21 = w2[c2 * 3 + 1], w22 = w2[c2 * 3 + 2];
    const float k2  = gamma2[c2] * rsqrtf(1.0f + 1e-5f);
    const float bb2 = beta2[c2];
    const unsigned long long W10 = pk2(w10, w10), W11 = pk2(w11, w11), W12 = pk2(w12, w12);
    const unsigned long long W20 = pk2(w20, w20), W21 = pk2(w21, w21), W22 = pk2(w22, w22);
    const unsigned long long K1 = pk2(k1, k1), B1 = pk2(bb1, bb1);
    const unsigned long long K2 = pk2(k2, k2), B2 = pk2(bb2, bb2);
    __half* z1h = (__half*)sx;   // [17][512] halves

    for (int i = tid; i < 2176; i += 768) {
        int n  = i >> 7;
        int f0 = (i & 127) << 2;
        float4 hi = *(float4*)(sh + ((f0 >> 6) * 17 + n) * 68 + (f0 & 63));
        float4 lo = make_float4(0.f, 0.f, 0.f, 0.f);
        if (f0 >= 4)
            lo = *(float4*)(sh + (((f0 - 4) >> 6) * 17 + n) * 68 + ((f0 - 4) & 63));
        unsigned long long P23 = pk2(lo.z, lo.w);
        unsigned long long P34 = pk2(lo.w, hi.x);
        unsigned long long P45 = pk2(hi.x, hi.y);
        unsigned long long P56 = pk2(hi.y, hi.z);
        unsigned long long P67 = pk2(hi.z, hi.w);
        unsigned long long y01 = mul2(W12, P45);
        y01 = fma2p(W11, P34, y01);
        y01 = fma2p(W10, P23, y01);
        unsigned long long y23 = mul2(W12, P67);
        y23 = fma2p(W11, P56, y23);
        y23 = fma2p(W10, P45, y23);
        y01 = fma2p(y01, K1, B1);
        y23 = fma2p(y23, K1, B1);
        uint2 hz;
        hz.x = p2_to_h2(gelu2(y01, C0447, C0798, ONE2, HALF2));
        hz.y = p2_to_h2(gelu2(y23, C0447, C0798, ONE2, HALF2));
        *(uint2*)(z1h + n * 512 + f0) = hz;
    }
    __syncthreads();

    // ---- phase 7: conv2 (k=3,d=2 causal) + BN + GELU -> fp16 scratch ----
    // 8 outputs per task; z1 in fp16, one LDS.64 + one LDS.128 per task.
    __half* out_b = g_scratch_h + (size_t)blockIdx.x * (Nn * Tt);
    for (int i = tid; i < 1088; i += 768) {
        int n  = i >> 6;
        int f0 = (i & 63) << 3;
        const __half* zp = z1h + n * 512 + f0;
        uint2 lo2 = make_uint2(0u, 0u);
        if (f0 >= 4) lo2 = *(const uint2*)(zp - 4);
        uint4 hi4 = *(const uint4*)zp;
        unsigned long long P0 = h2_to_p2(lo2.x);   // f0-4, f0-3
        unsigned long long P1 = h2_to_p2(lo2.y);   // f0-2, f0-1
        unsigned long long P2 = h2_to_p2(hi4.x);   // f0,   f0+1
        unsigned long long P3 = h2_to_p2(hi4.y);
        unsigned long long P4 = h2_to_p2(hi4.z);
        unsigned long long P5 = h2_to_p2(hi4.w);
        unsigned long long y0 = fma2p(W20, P0, fma2p(W21, P1, mul2(W22, P2)));
        unsigned long long y1 = fma2p(W20, P1, fma2p(W21, P2, mul2(W22, P3)));
        unsigned long long y2 = fma2p(W20, P2, fma2p(W21, P3, mul2(W22, P4)));
        unsigned long long y3 = fma2p(W20, P3, fma2p(W21, P4, mul2(W22, P5)));
        y0 = fma2p(y0, K2, B2);
        y1 = fma2p(y1, K2, B2);
        y2 = fma2p(y2, K2, B2);
        y3 = fma2p(y3, K2, B2);
        uint4 hv;
        hv.x = p2_to_h2(gelu2(y0, C0447, C0798, ONE2, HALF2));
        hv.y = p2_to_h2(gelu2(y1, C0447, C0798, ONE2, HALF2));
        hv.z = p2_to_h2(gelu2(y2, C0447, C0798, ONE2, HALF2));
        hv.w = p2_to_h2(gelu2(y3, C0447, C0798, ONE2, HALF2));
        *(uint4*)(out_b + n * 512 + f0) = hv;
    }
}

// ---------------------------------------------------------------------------
// Kernel B (identical to R13): transpose fp16 scratch -> fp32 out + residual.
// ---------------------------------------------------------------------------
__global__ void __launch_bounds__(512, 3) stconv_finalize(
    const float* __restrict__ x, float* __restrict__ out)
{
    extern __shared__ float sm[];
    float*  sxB = sm;                       // [8][1156] floats
    __half* sB  = (__half*)(sm + 9248);     // [8][1092] halves

    const int tid = threadIdx.x;
    const int b   = 63 - (blockIdx.x >> 6);
    const int jt  = blockIdx.x & 63;
    const int t0  = jt << 3;
    const bool xtra  = (tid < 128);
    const bool xtra2 = (tid < 64);

    float4 xr[4], xr4;
    uint4  sr[2], sr4;
#pragma unroll
    for (int k = 0; k < 4; ++k) {
        int i = tid + k * 512;
        int q = i & 15, t = (i >> 4) & 7, n = i >> 7;
        xr[k] = *(const float4*)(x + ((size_t)(b * Nn + n) * Tt + t0 + t) * Cc + q * 4);
    }
    if (xtra) {
        int i = tid + 2048;
        int q = i & 15, t = (i >> 4) & 7, n = i >> 7;
        xr4 = *(const float4*)(x + ((size_t)(b * Nn + n) * Tt + t0 + t) * Cc + q * 4);
    }
#pragma unroll
    for (int k = 0; k < 2; ++k) {
        int r = tid + k * 512;
        sr[k] = *(const uint4*)(g_scratch_h + (size_t)(b * 1088 + r) * Tt + t0);
    }
    if (xtra2) {
        int r = tid + 1024;
        sr4 = *(const uint4*)(g_scratch_h + (size_t)(b * 1088 + r) * Tt + t0);
    }

#pragma unroll
    for (int k = 0; k < 4; ++k) {
        int i = tid + k * 512;
        int q = i & 15, t = (i >> 4) & 7, n = i >> 7;
        *(float4*)(sxB + t * 1156 + n * 68 + q * 4) = xr[k];
    }
    if (xtra) {
        int i = tid + 2048;
        int q = i & 15, t = (i >> 4) & 7, n = i >> 7;
        *(float4*)(sxB + t * 1156 + n * 68 + q * 4) = xr4;
    }
#pragma unroll
    for (int k = 0; k < 2; ++k) {
        int r = tid + k * 512;
        const unsigned w[4] = {sr[k].x, sr[k].y, sr[k].z, sr[k].w};
#pragma unroll
        for (int q = 0; q < 4; ++q) {
            __half2 h = *(const __half2*)&w[q];
            sB[(2 * q + 0) * 1092 + r] = __low2half(h);
            sB[(2 * q + 1) * 1092 + r] = __high2half(h);
        }
    }
    if (xtra2) {
        int r = tid + 1024;
        const unsigned w[4] = {sr4.x, sr4.y, sr4.z, sr4.w};
#pragma unroll
        for (int q = 0; q < 4; ++q) {
            __half2 h = *(const __half2*)&w[q];
            sB[(2 * q + 0) * 1092 + r] = __low2half(h);
            sB[(2 * q + 1) * 1092 + r] = __high2half(h);
        }
    }
    __syncthreads();

    for (int i = tid; i < 2176; i += 512) {
        int q = i & 15;
        int t = (i >> 4) & 7;
        int n = i >> 7;
        float4 r4;
        float* rp = &r4.x;
#pragma unroll
        for (int k = 0; k < 4; ++k) {
            int c = q * 4 + k;
            int p = n * 64 + c;
            int c_src = p / 17;
            int n_src = p - c_src * 17;
            rp[k] = __half2float(sB[t * 1092 + c * 17 + n]) + sxB[t * 1156 + n_src * 68 + c_src];
        }
        *(float4*)(out + ((size_t)(b * Nn + n) * Tt + t0 + t) * Cc + q * 4) = r4;
    }
}

extern "C" void kernel_launch(void* const* d_in, const int* in_sizes, int n_in,
                              void* d_out, int out_size)
{
    const float* x      = (const float*)d_in[0];
    const int*   adj    = (const int*)d_in[1];
    const float* W      = (const float*)d_in[2];
    const float* av     = (const float*)d_in[3];
    const float* w1     = (const float*)d_in[4];
    const float* gamma1 = (const float*)d_in[5];
    const float* beta1  = (const float*)d_in[6];
    const float* w2     = (const float*)d_in[7];
    const float* gamma2 = (const float*)d_in[8];
    const float* beta2  = (const float*)d_in[9];
    float* out = (float*)d_out;

    const int smemA = SMEM_A_FLOATS * 4;            // 101,392 B
    const int smemB = 9248 * 4 + 8736 * 2;          // 54,464 B
    cudaFuncSetAttribute(stconv_gat_tcn,  cudaFuncAttributeMaxDynamicSharedMemorySize, smemA);
    cudaFuncSetAttribute(stconv_finalize, cudaFuncAttributeMaxDynamicSharedMemorySize, smemB);

    stconv_gat_tcn<<<Bb * 64, 768, smemA>>>(x, adj, W, av, w1, gamma1, beta1, w2, gamma2, beta2);
    stconv_finalize<<<Bb * 64, 512, smemB>>>(x, out);
}

// round 16
// speedup vs baseline: 1.0592x; 1.0592x over previous
#include <cuda_runtime.h>
#include <cuda_fp16.h>
#include <cstdint>

#define Bb 64
#define Nn 17
#define Tt 512
#define Cc 64

// scratch: [B][64(c2)][17(n)][512(t)] in fp16 (71MB)
__device__ __half g_scratch_h[Bb * 64 * Nn * Tt];

// ---------------- packed f32x2 helpers (sm_10x) ----------------------------
__device__ __forceinline__ unsigned long long pk2(float lo, float hi) {
    unsigned long long r;
    asm("mov.b64 %0, {%1, %2};" : "=l"(r) : "f"(lo), "f"(hi));
    return r;
}
__device__ __forceinline__ void upk2(unsigned long long v, float& lo, float& hi) {
    asm("mov.b64 {%0, %1}, %2;" : "=f"(lo), "=f"(hi) : "l"(v));
}
__device__ __forceinline__ unsigned long long mul2(unsigned long long a, unsigned long long b) {
    unsigned long long r;
    asm("mul.rn.f32x2 %0, %1, %2;" : "=l"(r) : "l"(a), "l"(b));
    return r;
}
__device__ __forceinline__ unsigned long long fma2p(unsigned long long a, unsigned long long b, unsigned long long c) {
    unsigned long long r;
    asm("fma.rn.f32x2 %0, %1, %2, %3;" : "=l"(r) : "l"(a), "l"(b), "l"(c));
    return r;
}
__device__ __forceinline__ float tanh_ap(float x) {
    float r;
    asm("tanh.approx.f32 %0, %1;" : "=f"(r) : "f"(x));
    return r;
}
__device__ __forceinline__ unsigned long long gelu2(unsigned long long z,
    unsigned long long C0447, unsigned long long C0798, unsigned long long ONE2, unsigned long long HALF2)
{
    unsigned long long w = mul2(z, z);
    unsigned long long p = fma2p(w, C0447, ONE2);
    unsigned long long q = mul2(z, C0798);
    unsigned long long u = mul2(p, q);
    float u0, u1; upk2(u, u0, u1);
    unsigned long long tp = pk2(tanh_ap(u0), tanh_ap(u1));
    unsigned long long hv = mul2(z, HALF2);
    return fma2p(tp, hv, hv);
}

__device__ __forceinline__ unsigned to_tf32(float f) {
    unsigned r;
    asm("cvt.rna.tf32.f32 %0, %1;" : "=r"(r) : "f"(f));
    return r;
}

// half2-word (uint) -> packed f32x2
__device__ __forceinline__ unsigned long long h2_to_p2(unsigned hv) {
    __half2 h = *(__half2*)&hv;
    float2 f = __half22float2(h);
    return pk2(f.x, f.y);
}
// packed f32x2 -> half2 word
__device__ __forceinline__ unsigned p2_to_h2(unsigned long long p) {
    float lo, hi; upk2(p, lo, hi);
    __half2 h = __floats2half2_rn(lo, hi);
    return *(unsigned*)&h;
}
__device__ __forceinline__ float2 h2f2(unsigned w) {
    return __half22float2(*(__half2*)&w);
}
__device__ __forceinline__ unsigned f2h2(float a, float b) {
    __half2 h = __floats2half2_rn(a, b);
    return *(unsigned*)&h;
}

// ---------------------------------------------------------------------------
// Kernel A: one block per (b, c2).  512 threads x 3 CTAs/SM.
// sx, sh stored as fp16 word arrays [136][36 words] (stride 36 uints).
// ---------------------------------------------------------------------------
#define OFF_SXH   0              /* 4896 uints: halves [136][72], 68 used */
#define OFF_SHH   4896           /* 4896 uints */
#define OFF_SW    9792           /* [64][68] fp32 tf32-rounded */
#define OFF_BIAS  14144          /* 289 used, padded 292 */
#define OFF_SS    14436
#define OFF_ST    14980
#define OFF_DIV   15524
#define OFF_SCL   16068
#define OFF_SA    16612
#define SMEM_A_FLOATS 16644

__global__ void __launch_bounds__(512, 3) stconv_gat_tcn(
    const float* __restrict__ x, const int* __restrict__ adj,
    const float* __restrict__ W, const float* __restrict__ av,
    const float* __restrict__ w1, const float* __restrict__ gamma1, const float* __restrict__ beta1,
    const float* __restrict__ w2, const float* __restrict__ gamma2, const float* __restrict__ beta2)
{
    extern __shared__ float sm[];
    unsigned* sxw   = (unsigned*)(sm + OFF_SXH);   // x as half2 words
    unsigned* shw   = (unsigned*)(sm + OFF_SHH);   // h/g as half2 words
    float* sW    = sm + OFF_SW;
    float* sbias = sm + OFF_BIAS;
    float* ss    = sm + OFF_SS;
    float* st    = sm + OFF_ST;
    float* sdiv  = sm + OFF_DIV;
    float* sscl  = sm + OFF_SCL;
    float* sa    = sm + OFF_SA;

    const int tid = threadIdx.x;
    const int b   = blockIdx.x >> 6;
    const int c2  = blockIdx.x & 63;
    const int t0  = c2 << 3;

    // ---- phase 1: loads -------------------------------------------------
    {
        const float4* xg = (const float4*)(x + ((size_t)(b * Nn) * Tt + t0) * Cc);
        for (int i = tid; i < 2176; i += 512) {
            int q  = i & 15;
            int nt = i >> 4;
            int n  = nt % 17;
            int t  = nt / 17;
            float4 v = xg[((size_t)n * Tt + t) * 16 + q];
            uint2 u;
            u.x = f2h2(v.x, v.y);
            u.y = f2h2(v.z, v.w);
            *(uint2*)(sxw + (t * 17 + n) * 36 + q * 2) = u;
        }
        for (int i = tid; i < 1024; i += 512) {
            int o = i >> 4, c4 = i & 15;
            float4 v = ((const float4*)W)[i];
            v.x = __uint_as_float(to_tf32(v.x));
            v.y = __uint_as_float(to_tf32(v.y));
            v.z = __uint_as_float(to_tf32(v.z));
            v.w = __uint_as_float(to_tf32(v.w));
            *(float4*)(sW + o * 68 + c4 * 4) = v;
        }
        if (tid < 289)
            sbias[tid] = (adj[b * 289 + tid] == 0) ? -1e9f : 0.0f;
        if (tid < 32) sa[tid] = av[tid];
    }
    __syncthreads();

    // ---- phase 2: GEMM h = x * W^T (tf32 MMA, m16n16 units, fp16 A) -----
    {
        const int warp = tid >> 5, lane = tid & 31;
        const int lr = lane >> 2, lc = lane & 3;
        const int hsh = (lc & 1) * 16;
        for (int unit = warp; unit < 36; unit += 16) {
            const int mt = unit >> 2;
            const int nq = unit & 3;
            const int m0 = mt << 4;
            const int r0 = m0 + lr;
            const int r1 = (r0 + 8 < 136) ? (r0 + 8) : 135;
            float d[8];
#pragma unroll
            for (int i = 0; i < 8; ++i) d[i] = 0.0f;
#pragma unroll
            for (int k0 = 0; k0 < 8; ++k0) {
                const int kb = k0 * 8 + lc;
                const int w0 = k0 * 4 + (lc >> 1);
                unsigned u00 = sxw[r0 * 36 + w0];
                unsigned u01 = sxw[r0 * 36 + w0 + 2];
                unsigned u10 = sxw[r1 * 36 + w0];
                unsigned u11 = sxw[r1 * 36 + w0 + 2];
                unsigned a0 = __float_as_uint(__half2float(__ushort_as_half((unsigned short)(u00 >> hsh))));
                unsigned a1 = __float_as_uint(__half2float(__ushort_as_half((unsigned short)(u10 >> hsh))));
                unsigned a2 = __float_as_uint(__half2float(__ushort_as_half((unsigned short)(u01 >> hsh))));
                unsigned a3 = __float_as_uint(__half2float(__ushort_as_half((unsigned short)(u11 >> hsh))));
#pragma unroll
                for (int j8 = 0; j8 < 2; ++j8) {
                    const int n = nq * 16 + j8 * 8 + lr;
                    unsigned b0 = __float_as_uint(sW[n * 68 + kb]);
                    unsigned b1 = __float_as_uint(sW[n * 68 + kb + 4]);
                    asm("mma.sync.aligned.m16n8k8.row.col.f32.tf32.tf32.f32 "
                        "{%0,%1,%2,%3},{%4,%5,%6,%7},{%8,%9},{%0,%1,%2,%3};"
                        : "+f"(d[j8*4+0]), "+f"(d[j8*4+1]), "+f"(d[j8*4+2]), "+f"(d[j8*4+3])
                        : "r"(a0), "r"(a1), "r"(a2), "r"(a3), "r"(b0), "r"(b1));
                }
            }
#pragma unroll
            for (int j8 = 0; j8 < 2; ++j8) {
                const int colw = nq * 8 + j8 * 4 + lc;
                shw[r0 * 36 + colw] = f2h2(d[j8*4+0], d[j8*4+1]);
                if (mt < 8)
                    shw[(m0 + 8 + lr) * 36 + colw] = f2h2(d[j8*4+2], d[j8*4+3]);
            }
        }
    }
    __syncthreads();

    // ---- phase 3: per-head source/target dots ---------------------------
    for (int i = tid; i < 1088; i += 512) {
        int kind = i & 1;
        int hd   = (i >> 1) & 3;
        int row  = i >> 3;
        uint4 wa = *(const uint4*)(shw + row * 36 + hd * 8);
        uint4 wb = *(const uint4*)(shw + row * 36 + hd * 8 + 4);
        const float* ap = sa + kind * 16;
        float2 f0 = h2f2(wa.x), f1 = h2f2(wa.y), f2 = h2f2(wa.z), f3 = h2f2(wa.w);
        float2 f4 = h2f2(wb.x), f5 = h2f2(wb.y), f6 = h2f2(wb.z), f7 = h2f2(wb.w);
        float acc = 0.0f;
        acc = fmaf(f0.x, ap[0], acc);  acc = fmaf(f0.y, ap[1], acc);
        acc = fmaf(f1.x, ap[2], acc);  acc = fmaf(f1.y, ap[3], acc);
        acc = fmaf(f2.x, ap[4], acc);  acc = fmaf(f2.y, ap[5], acc);
        acc = fmaf(f3.x, ap[6], acc);  acc = fmaf(f3.y, ap[7], acc);
        acc = fmaf(f4.x, ap[8], acc);  acc = fmaf(f4.y, ap[9], acc);
        acc = fmaf(f5.x, ap[10], acc); acc = fmaf(f5.y, ap[11], acc);
        acc = fmaf(f6.x, ap[12], acc); acc = fmaf(f6.y, ap[13], acc);
        acc = fmaf(f7.x, ap[14], acc); acc = fmaf(f7.y, ap[15], acc);
        (kind ? st : ss)[row * 4 + hd] = acc;
    }
    __syncthreads();

    // ---- phase 4a: per-(i,h) inv-denominator ----------------------------
    for (int task = tid; task < 544; task += 512) {
        int hd  = task & 3;
        int row = task >> 2;
        int t   = row / 17;
        int ii  = row - t * 17;
        float sv = ss[row * 4 + hd];
        float den = 0.0f;
#pragma unroll
        for (int j = 0; j < 17; ++j) {
            float e = sv + st[(t * 17 + j) * 4 + hd];
            e = (e > 0.0f) ? e : 0.2f * e;
            den += __expf(e + sbias[ii * 17 + j]);
        }
        sdiv[row * 4 + hd] = __fdividef(1.0f, den);
    }
    __syncthreads();

    // ---- phase 4b: scale[j] = sum_i alpha[i][j] -------------------------
    for (int task = tid; task < 544; task += 512) {
        int hd  = task & 3;
        int row = task >> 2;
        int t   = row / 17;
        int jj  = row - t * 17;
        float tv = st[row * 4 + hd];
        float acc = 0.0f;
#pragma unroll
        for (int i = 0; i < 17; ++i) {
            int ri = (t * 17 + i) * 4 + hd;
            float e = ss[ri] + tv;
            e = (e > 0.0f) ? e : 0.2f * e;
            acc = fmaf(__expf(e + sbias[i * 17 + jj]), sdiv[ri], acc);
        }
        sscl[row * 4 + hd] = acc;
    }
    __syncthreads();

    // ---- phase 5: g = h*scale + h0  (fp32 math, fp16 storage) -----------
    for (int i = tid; i < 1088; i += 512) {
        int row = i >> 3;
        int c0  = (i & 7) << 3;          // 0..56
        int wb  = c0 >> 1;               // word base (mult of 4)
        uint4 hw = *(const uint4*)(shw + row * 36 + wb);
        uint4 xw = *(const uint4*)(sxw + row * 36 + wb);
        float sc = sscl[row * 4 + (c0 >> 4)];
        float2 h0 = h2f2(hw.x), h1 = h2f2(hw.y), h2 = h2f2(hw.z), h3 = h2f2(hw.w);
        float2 x0 = h2f2(xw.x), x1 = h2f2(xw.y), x2 = h2f2(xw.z), x3 = h2f2(xw.w);
        uint4 gw;
        gw.x = f2h2(fmaf(h0.x, sc, x0.x), fmaf(h0.y, sc, x0.y));
        gw.y = f2h2(fmaf(h1.x, sc, x1.x), fmaf(h1.y, sc, x1.y));
        gw.z = f2h2(fmaf(h2.x, sc, x2.x), fmaf(h2.y, sc, x2.y));
        gw.w = f2h2(fmaf(h3.x, sc, x3.x), fmaf(h3.y, sc, x3.y));
        *(uint4*)(shw + row * 36 + wb) = gw;
    }
    __syncthreads();

    const unsigned long long C0447 = pk2(0.044715f, 0.044715f);
    const unsigned long long C0798 = pk2(0.7978845608028654f, 0.7978845608028654f);
    const unsigned long long ONE2  = pk2(1.0f, 1.0f);
    const unsigned long long HALF2 = pk2(0.5f, 0.5f);

    const float w10 = w1[c2 * 3 + 0], w11 = w1[c2 * 3 + 1], w12 = w1[c2 * 3 + 2];
    const float k1  = gamma1[c2] * rsqrtf(1.0f + 1e-5f);
    const float bb1 = beta1[c2];
    const float w20 = w2[c2 * 3 + 0], w21 = w2[c2 * 3 + 1], w22 = w2[c2 * 3 + 2];
    const float k2  = gamma2[c2] * rsqrtf(1.0f + 1e-5f);
    const float bb2 = beta2[c2];
    const unsigned long long W10 = pk2(w10, w10), W11 = pk2(w11, w11), W12 = pk2(w12, w12);
    const unsigned long long W20 = pk2(w20, w20), W21 = pk2(w21, w21), W22 = pk2(w22, w22);
    const unsigned long long K1 = pk2(k1, k1), B1 = pk2(bb1, bb1);
    const unsigned long long K2 = pk2(k2, k2), B2 = pk2(bb2, bb2);

    // z1 lives in the SXH region: [17][512] halves = [17][256] words
    unsigned* z1w = sxw;
    __half*   z1h = (__half*)sxw;

    // ---- phase 6: conv1 (k=3,d=1 causal) + BN + GELU -> z1 --------------
    // 8 outputs per task: g[f0-2..f0+7], main 8 in one row (f0 mult of 8).
    for (int i = tid; i < 1088; i += 512) {
        int n  = i >> 6;
        int f0 = (i & 63) << 3;
        int rowm = (f0 >> 6) * 17 + n;
        int cm   = f0 & 63;
        uint4 m4 = *(const uint4*)(shw + rowm * 36 + (cm >> 1));
        unsigned pw = 0u;
        if (f0 >= 2) {
            int fp = f0 - 2;
            int rowp = (fp >> 6) * 17 + n;
            pw = shw[rowp * 36 + ((fp & 63) >> 1)];
        }
        float2 m  = h2f2(pw);                       // g(f0-2), g(f0-1)
        float2 a01 = h2f2(m4.x), a23 = h2f2(m4.y), a45 = h2f2(m4.z), a67 = h2f2(m4.w);
        unsigned long long Pm  = pk2(m.x, m.y);
        unsigned long long P01 = pk2(a01.x, a01.y);
        unsigned long long P23 = pk2(a23.x, a23.y);
        unsigned long long P45 = pk2(a45.x, a45.y);
        unsigned long long P67 = pk2(a67.x, a67.y);
        unsigned long long Sm0 = pk2(m.y, a01.x);
        unsigned long long S12 = pk2(a01.y, a23.x);
        unsigned long long S34 = pk2(a23.y, a45.x);
        unsigned long long S56 = pk2(a45.y, a67.x);
        unsigned long long y0 = fma2p(W10, Pm,  fma2p(W11, Sm0, mul2(W12, P01)));
        unsigned long long y1 = fma2p(W10, P01, fma2p(W11, S12, mul2(W12, P23)));
        unsigned long long y2 = fma2p(W10, P23, fma2p(W11, S34, mul2(W12, P45)));
        unsigned long long y3 = fma2p(W10, P45, fma2p(W11, S56, mul2(W12, P67)));
        y0 = fma2p(y0, K1, B1);
        y1 = fma2p(y1, K1, B1);
        y2 = fma2p(y2, K1, B1);
        y3 = fma2p(y3, K1, B1);
        uint4 zv;
        zv.x = p2_to_h2(gelu2(y0, C0447, C0798, ONE2, HALF2));
        zv.y = p2_to_h2(gelu2(y1, C0447, C0798, ONE2, HALF2));
        zv.z = p2_to_h2(gelu2(y2, C0447, C0798, ONE2, HALF2));
        zv.w = p2_to_h2(gelu2(y3, C0447, C0798, ONE2, HALF2));
        *(uint4*)(z1w + n * 256 + (f0 >> 1)) = zv;
    }
    __syncthreads();

    // ---- phase 7: conv2 (k=3,d=2 causal) + BN + GELU -> fp16 scratch ----
    __half* out_b = g_scratch_h + (size_t)blockIdx.x * (Nn * Tt);
    for (int i = tid; i < 1088; i += 512) {
        int n  = i >> 6;
        int f0 = (i & 63) << 3;
        const __half* zp = z1h + n * 512 + f0;
        uint2 lo2 = make_uint2(0u, 0u);
        if (f0 >= 4) lo2 = *(const uint2*)(zp - 4);
        uint4 hi4 = *(const uint4*)zp;
        unsigned long long P0 = h2_to_p2(lo2.x);
        unsigned long long P1 = h2_to_p2(lo2.y);
        unsigned long long P2 = h2_to_p2(hi4.x);
        unsigned long long P3 = h2_to_p2(hi4.y);
        unsigned long long P4 = h2_to_p2(hi4.z);
        unsigned long long P5 = h2_to_p2(hi4.w);
        unsigned long long y0 = fma2p(W20, P0, fma2p(W21, P1, mul2(W22, P2)));
        unsigned long long y1 = fma2p(W20, P1, fma2p(W21, P2, mul2(W22, P3)));
        unsigned long long y2 = fma2p(W20, P2, fma2p(W21, P3, mul2(W22, P4)));
        unsigned long long y3 = fma2p(W20, P3, fma2p(W21, P4, mul2(W22, P5)));
        y0 = fma2p(y0, K2, B2);
        y1 = fma2p(y1, K2, B2);
        y2 = fma2p(y2, K2, B2);
        y3 = fma2p(y3, K2, B2);
        uint4 hv;
        hv.x = p2_to_h2(gelu2(y0, C0447, C0798, ONE2, HALF2));
        hv.y = p2_to_h2(gelu2(y1, C0447, C0798, ONE2, HALF2));
        hv.z = p2_to_h2(gelu2(y2, C0447, C0798, ONE2, HALF2));
        hv.w = p2_to_h2(gelu2(y3, C0447, C0798, ONE2, HALF2));
        *(uint4*)(out_b + n * 512 + f0) = hv;
    }
}

// ---------------------------------------------------------------------------
// Kernel B (identical to R13): transpose fp16 scratch -> fp32 out + residual.
// ---------------------------------------------------------------------------
__global__ void __launch_bounds__(512, 3) stconv_finalize(
    const float* __restrict__ x, float* __restrict__ out)
{
    extern __shared__ float sm[];
    float*  sxB = sm;                       // [8][1156] floats
    __half* sB  = (__half*)(sm + 9248);     // [8][1092] halves

    const int tid = threadIdx.x;
    const int b   = 63 - (blockIdx.x >> 6);
    const int jt  = blockIdx.x & 63;
    const int t0  = jt << 3;
    const bool xtra  = (tid < 128);
    const bool xtra2 = (tid < 64);

    float4 xr[4], xr4;
    uint4  sr[2], sr4;
#pragma unroll
    for (int k = 0; k < 4; ++k) {
        int i = tid + k * 512;
        int q = i & 15, t = (i >> 4) & 7, n = i >> 7;
        xr[k] = *(const float4*)(x + ((size_t)(b * Nn + n) * Tt + t0 + t) * Cc + q * 4);
    }
    if (xtra) {
        int i = tid + 2048;
        int q = i & 15, t = (i >> 4) & 7, n = i >> 7;
        xr4 = *(const float4*)(x + ((size_t)(b * Nn + n) * Tt + t0 + t) * Cc + q * 4);
    }
#pragma unroll
    for (int k = 0; k < 2; ++k) {
        int r = tid + k * 512;
        sr[k] = *(const uint4*)(g_scratch_h + (size_t)(b * 1088 + r) * Tt + t0);
    }
    if (xtra2) {
        int r = tid + 1024;
        sr4 = *(const uint4*)(g_scratch_h + (size_t)(b * 1088 + r) * Tt + t0);
    }

#pragma unroll
    for (int k = 0; k < 4; ++k) {
        int i = tid + k * 512;
        int q = i & 15, t = (i >> 4) & 7, n = i >> 7;
        *(float4*)(sxB + t * 1156 + n * 68 + q * 4) = xr[k];
    }
    if (xtra) {
        int i = tid + 2048;
        int q = i & 15, t = (i >> 4) & 7, n = i >> 7;
        *(float4*)(sxB + t * 1156 + n * 68 + q * 4) = xr4;
    }
#pragma unroll
    for (int k = 0; k < 2; ++k) {
        int r = tid + k * 512;
        const unsigned w[4] = {sr[k].x, sr[k].y, sr[k].z, sr[k].w};
#pragma unroll
        for (int q = 0; q < 4; ++q) {
            __half2 h = *(const __half2*)&w[q];
            sB[(2 * q + 0) * 1092 + r] = __low2half(h);
            sB[(2 * q + 1) * 1092 + r] = __high2half(h);
        }
    }
    if (xtra2) {
        int r = tid + 1024;
        const unsigned w[4] = {sr4.x, sr4.y, sr4.z, sr4.w};
#pragma unroll
        for (int q = 0; q < 4; ++q) {
            __half2 h = *(const __half2*)&w[q];
            sB[(2 * q + 0) * 1092 + r] = __low2half(h);
            sB[(2 * q + 1) * 1092 + r] = __high2half(h);
        }
    }
    __syncthreads();

    for (int i = tid; i < 2176; i += 512) {
        int q = i & 15;
        int t = (i >> 4) & 7;
        int n = i >> 7;
        float4 r4;
        float* rp = &r4.x;
#pragma unroll
        for (int k = 0; k < 4; ++k) {
            int c = q * 4 + k;
            int p = n * 64 + c;
            int c_src = p / 17;
            int n_src = p - c_src * 17;
            rp[k] = __half2float(sB[t * 1092 + c * 17 + n]) + sxB[t * 1156 + n_src * 68 + c_src];
        }
        *(float4*)(out + ((size_t)(b * Nn + n) * Tt + t0 + t) * Cc + q * 4) = r4;
    }
}

extern "C" void kernel_launch(void* const* d_in, const int* in_sizes, int n_in,
                              void* d_out, int out_size)
{
    const float* x      = (const float*)d_in[0];
    const int*   adj    = (const int*)d_in[1];
    const float* W      = (const float*)d_in[2];
    const float* av     = (const float*)d_in[3];
    const float* w1     = (const float*)d_in[4];
    const float* gamma1 = (const float*)d_in[5];
    const float* beta1  = (const float*)d_in[6];
    const float* w2     = (const float*)d_in[7];
    const float* gamma2 = (const float*)d_in[8];
    const float* beta2  = (const float*)d_in[9];
    float* out = (float*)d_out;

    const int smemA = SMEM_A_FLOATS * 4;            // 66,576 B
    const int smemB = 9248 * 4 + 8736 * 2;          // 54,464 B
    cudaFuncSetAttribute(stconv_gat_tcn,  cudaFuncAttributeMaxDynamicSharedMemorySize, smemA);
    cudaFuncSetAttribute(stconv_finalize, cudaFuncAttributeMaxDynamicSharedMemorySize, smemB);

    stconv_gat_tcn<<<Bb * 64, 512, smemA>>>(x, adj, W, av, w1, gamma1, beta1, w2, gamma2, beta2);
    stconv_finalize<<<Bb * 64, 512, smemB>>>(x, out);
}